// round 8
// baseline (speedup 1.0000x reference)
#include <cuda_runtime.h>
#include <cuda_fp16.h>
#include <math.h>
#include <stdint.h>

#define Bdim 16
#define Ndim 128
#define Cdim 256
#define BN   2048
#define INVS 0.1767766952966369f

// ---------------- device globals ----------------
__device__ float g_q[BN*Cdim];
__device__ float g_k[BN*Cdim];
__device__ __align__(16) __half g_v16[BN*Cdim];
__device__ float g_WonT[Cdim*Cdim];
__device__ __align__(16) __half g_We_h[Cdim*Cdim];
__device__ __align__(16) __half g_Woe_h[Cdim*Cdim];
__device__ float g_ps [2*BN*Cdim];   // softmax partial sums
__device__ float g_pag[2*BN*Cdim];   // weighted-v partial sums
__device__ int   g_cnt[BN];          // zero-init; self-resetting per launch

// ---------------- smem layout (bytes) ----------------
#define EDG   0        // edge fp16 [64][264h] stride 528      = 33792
#define ATT   33792    // attn fp16 4 chunks x [64][72h] s144  = 36864
#define WB    70656    // weight buf [64][264h] stride 528     = 33792
#define SQ_   104448
#define SBE_  105472
#define SBOE_ 106496
#define SAGG_ 107520
#define ESMEM 108544

// ---------------- PTX helpers ----------------
__device__ __forceinline__ uint32_t smem_u32(const void* p) {
    uint32_t a;
    asm("{ .reg .u64 t; cvta.to.shared.u64 t, %1; cvt.u32.u64 %0, t; }" : "=r"(a) : "l"(p));
    return a;
}
__device__ __forceinline__ void ldm4(uint32_t addr, uint32_t r[4]) {
    asm volatile("ldmatrix.sync.aligned.m8n8.x4.shared.b16 {%0,%1,%2,%3}, [%4];"
                 : "=r"(r[0]), "=r"(r[1]), "=r"(r[2]), "=r"(r[3]) : "r"(addr));
}
__device__ __forceinline__ void mma_f16(float d[4], const uint32_t a[4],
                                        uint32_t b0, uint32_t b1) {
    asm volatile("mma.sync.aligned.m16n8k16.row.col.f32.f16.f16.f32 "
                 "{%0,%1,%2,%3}, {%4,%5,%6,%7}, {%8,%9}, {%0,%1,%2,%3};"
                 : "+f"(d[0]), "+f"(d[1]), "+f"(d[2]), "+f"(d[3])
                 : "r"(a[0]), "r"(a[1]), "r"(a[2]), "r"(a[3]), "r"(b0), "r"(b1));
}
__device__ __forceinline__ uint32_t hpk(float a, float b) {
    __half2 t = __floats2half2_rn(a, b);
    return *reinterpret_cast<uint32_t*>(&t);
}
__device__ __forceinline__ void cp16(uint32_t d, const void* s) {
    asm volatile("cp.async.cg.shared.global [%0], [%1], 16;" :: "r"(d), "l"(s));
}
#define CP_COMMIT asm volatile("cp.async.commit_group;" ::: "memory")
#define CP_WAIT0  asm volatile("cp.async.wait_group 0;" ::: "memory")

// ---------------- weight prep ----------------
__global__ void prep_w(const float* __restrict__ We, const float* __restrict__ Woe,
                       const float* __restrict__ Won) {
    int n = blockIdx.x, w = blockIdx.y, k = threadIdx.x;
    if (w == 2) { g_WonT[k*Cdim + n] = Won[n*Cdim + k]; return; }
    const float* W = w ? Woe : We;
    __half hi = __float2half(W[n*Cdim + k]);
    if (w) g_Woe_h[n*Cdim+k] = hi;
    else   g_We_h [n*Cdim+k] = hi;
}

// ---------------- fp32 qkv projection ----------------
#define SASTR 36
#define SBSTR 260

__device__ __forceinline__ void load_tileA(float* sA, const float* __restrict__ X,
                                           int row0, int kc, int tid) {
    #pragma unroll
    for (int it = 0; it < 2; it++) {
        int idx = tid + it*256;
        int r = idx >> 3, k4 = idx & 7;
        float4 t = *(const float4*)(X + (size_t)(row0 + r)*Cdim + kc*32 + k4*4);
        *(float4*)(sA + r*SASTR + k4*4) = t;
    }
}
__device__ __forceinline__ void load_tileB(float* sB, const float* __restrict__ W,
                                           int kc, int tid) {
    #pragma unroll
    for (int it = 0; it < 8; it++) {
        int idx = tid + it*256;
        int c = idx >> 3, k4 = idx & 7;
        float4 t = *(const float4*)(W + c*Cdim + kc*32 + k4*4);
        sB[(k4*4+0)*SBSTR + c] = t.x;
        sB[(k4*4+1)*SBSTR + c] = t.y;
        sB[(k4*4+2)*SBSTR + c] = t.z;
        sB[(k4*4+3)*SBSTR + c] = t.w;
    }
}
__device__ __forceinline__ void mma_chunk_sA(const float* sA, const float* sB,
                                             float acc[8][8], int tx, int ty) {
    #pragma unroll
    for (int k = 0; k < 32; k++) {
        float a[8];
        #pragma unroll
        for (int mm = 0; mm < 4; mm++) {
            a[mm]   = sA[(ty*4+mm)*SASTR + k];
            a[4+mm] = sA[(32+ty*4+mm)*SASTR + k];
        }
        float4 p0 = *(const float4*)(sB + k*SBSTR + tx*4);
        float4 p1 = *(const float4*)(sB + k*SBSTR + 128 + tx*4);
        float bb[8] = {p0.x,p0.y,p0.z,p0.w,p1.x,p1.y,p1.z,p1.w};
        #pragma unroll
        for (int m = 0; m < 8; m++)
            #pragma unroll
            for (int n = 0; n < 8; n++)
                acc[m][n] = fmaf(a[m], bb[n], acc[m][n]);
    }
}

__global__ __launch_bounds__(256) void proj_kernel(
    const float* __restrict__ X,
    const float* __restrict__ W0, const float* __restrict__ b0,
    const float* __restrict__ W1, const float* __restrict__ b1,
    const float* __restrict__ W2, const float* __restrict__ b2)
{
    __shared__ float sA[64*SASTR];
    __shared__ float sB[32*SBSTR];
    int which = blockIdx.y;
    const float* W    = (which==0) ? W0 : (which==1 ? W1 : W2);
    const float* bias = (which==0) ? b0 : (which==1 ? b1 : b2);

    int tid = threadIdx.x;
    int tx = tid & 31, ty = tid >> 5;
    int row0 = blockIdx.x * 64;

    float acc[8][8];
    #pragma unroll
    for (int m = 0; m < 8; m++)
        #pragma unroll
        for (int n = 0; n < 8; n++) acc[m][n] = 0.f;

    for (int kc = 0; kc < 8; kc++) {
        __syncthreads();
        load_tileA(sA, X, row0, kc, tid);
        load_tileB(sB, W, kc, tid);
        __syncthreads();
        mma_chunk_sA(sA, sB, acc, tx, ty);
    }
    #pragma unroll
    for (int mh = 0; mh < 2; mh++)
    #pragma unroll
    for (int mm = 0; mm < 4; mm++) {
        int m = mh*4 + mm;
        int rloc = mh*32 + ty*4 + mm;
        size_t grow = (size_t)(row0 + rloc) * Cdim;
        #pragma unroll
        for (int nh = 0; nh < 2; nh++) {
            int col0 = nh*128 + tx*4;
            float4 o;
            o.x = acc[m][nh*4+0] + bias[col0+0];
            o.y = acc[m][nh*4+1] + bias[col0+1];
            o.z = acc[m][nh*4+2] + bias[col0+2];
            o.w = acc[m][nh*4+3] + bias[col0+3];
            if (which == 0)      *(float4*)(g_q + grow + col0) = o;
            else if (which == 1) *(float4*)(g_k + grow + col0) = o;
            else {
                __half2 h0 = __floats2half2_rn(o.x, o.y);
                __half2 h1 = __floats2half2_rn(o.z, o.w);
                uint2 u;
                u.x = *reinterpret_cast<uint32_t*>(&h0);
                u.y = *reinterpret_cast<uint32_t*>(&h1);
                *(uint2*)(g_v16 + grow + col0) = u;
            }
        }
    }
}

// ---------------- edge kernel: weight chunk loader (64 rows x 256 halfs) ----------------
__device__ __forceinline__ void loadW(uint32_t sb, const __half* src, int tid) {
    #pragma unroll
    for (int it = 0; it < 8; it++) {            // 64 rows x 32 parts
        int idx = tid + it*256;
        int row = idx >> 5, part = idx & 31;
        cp16(sb + WB + row*528 + part*16, src + row*Cdim + part*8);
    }
}

// ---------------- GEMM pass: M=64, N=64, K=256 (A from 'a' base, B from WB) ----------------
// A layout: either EDG ([64][264] s528, K contiguous) or ATT (4 chunks x [64][72] s144)
template<bool FROM_ATT>
__device__ __forceinline__ void gpass(uint32_t sb, uint32_t aoff, uint32_t atoff,
                                      uint32_t boff, float acc[4][4]) {
    uint32_t a[4], bh[4];
    #pragma unroll
    for (int ks = 0; ks < 16; ks++) {
        if (FROM_ATT) {
            int ch = ks >> 2, kk = ks & 3;
            ldm4(sb + ATT + ch*9216 + atoff + kk*32, a);
        } else {
            ldm4(sb + EDG + aoff + ks*32, a);
        }
        #pragma unroll
        for (int ntp = 0; ntp < 2; ntp++) {
            ldm4(sb + WB + boff + ntp*(16*528) + ks*32, bh);
            mma_f16(acc[ntp*2+0], a, bh[0], bh[1]);
            mma_f16(acc[ntp*2+1], a, bh[2], bh[3]);
        }
    }
}

// ---------------- fused edge mega-kernel: one CTA per (b,i,j-half) ----------------
__global__ __launch_bounds__(256, 2) void edge_fused(
    const float* __restrict__ edge,
    const float* __restrict__ be, const float* __restrict__ boe,
    const float* __restrict__ bon,
    float* __restrict__ edge_out, float* __restrict__ node_out)
{
    extern __shared__ char sm[];
    __shared__ int sWin;
    uint32_t sb = smem_u32(sm);
    const int tid  = threadIdx.x;
    const int lane = tid & 31, wid = tid >> 5;
    const int bi   = blockIdx.x >> 1;       // b*128 + i
    const int jh   = blockIdx.x & 1;        // j-half
    const int b    = bi >> 7;
    const int jrow0 = jh * 64;

    loadW(sb, g_We_h, tid);
    CP_COMMIT;

    float* sQ   = (float*)(sm + SQ_);
    float* sBe  = (float*)(sm + SBE_);
    float* sBoe = (float*)(sm + SBOE_);
    float* sAgg = (float*)(sm + SAGG_);
    sQ[tid]   = g_q[(size_t)bi*Cdim + tid];
    sBe[tid]  = be[tid];
    sBoe[tid] = boe[tid];

    // edge half-tile -> fp16 in smem (64 rows x 256 cols)
    const float4* erow = (const float4*)(edge + ((size_t)bi*Ndim + jrow0)*Cdim);
    #pragma unroll
    for (int it = 0; it < 16; it++) {
        int idx = tid + it*256;              // 0..4095 float4
        float4 v = erow[idx];
        int j = idx >> 6, c4 = idx & 63;
        __half2 h0 = __floats2half2_rn(v.x, v.y);
        __half2 h1 = __floats2half2_rn(v.z, v.w);
        uint2 u;
        u.x = *reinterpret_cast<uint32_t*>(&h0);
        u.y = *reinterpret_cast<uint32_t*>(&h1);
        *(uint2*)(sm + EDG + j*528 + c4*8) = u;
    }

    // fragment address offsets (8 warps: wm 0..3 m-tiles, wn 0..1 n-groups)
    const int wm = wid & 3, wn = wid >> 2;
    const int m0 = wm*16;
    const uint32_t aoff  = (uint32_t)((m0 + (lane & 15))*528 + ((lane >> 4) << 4));
    const uint32_t atoff = (uint32_t)((m0 + (lane & 15))*144 + ((lane >> 4) << 4));
    const uint32_t boff  = (uint32_t)((wn*32 + (lane & 7) + ((lane & 16) ? 8 : 0))*528 + ((lane & 8) << 1));

    const int r0 = m0 + (lane >> 2);         // local row 0..63

    // ================= Phase 1: GEMM1 + gating -> attn chunks =================
    for (int nc = 0; nc < 4; nc++) {
        float acc1[4][4];
        #pragma unroll
        for (int i = 0; i < 4; i++)
            #pragma unroll
            for (int r = 0; r < 4; r++) acc1[i][r] = 0.f;

        CP_WAIT0; __syncthreads();            // We(nc) ready (nc=0: +edge STS visible)
        gpass<false>(sb, aoff, atoff, boff, acc1);
        __syncthreads();                      // all done reading WB
        if (nc < 3) loadW(sb, g_We_h + (size_t)(nc+1)*64*Cdim, tid);
        else        loadW(sb, g_Woe_h, tid);
        CP_COMMIT;                            // overlaps gating epilogue (+softmax on nc=3)

        // ---- gating epilogue -> attn fp16 chunk nc ----
        #pragma unroll
        for (int nt = 0; nt < 4; nt++) {
            int c_loc = wn*32 + nt*8 + ((lane & 3) << 1);
            int c = nc*64 + c_loc;
            float q0 = sQ[c], q1 = sQ[c+1];
            float be0 = sBe[c], be1 = sBe[c+1];
            float2 k0 = *(const float2*)(g_k + (size_t)(b*Ndim + jrow0 + r0)*Cdim + c);
            float2 k1 = *(const float2*)(g_k + (size_t)(b*Ndim + jrow0 + r0 + 8)*Cdim + c);
            float e00 = acc1[nt][0] + be0, e01 = acc1[nt][1] + be1;
            float e10 = acc1[nt][2] + be0, e11 = acc1[nt][3] + be1;
            float a00 = q0*k0.x*INVS*(e00*e00 + e00);
            float a01 = q1*k0.y*INVS*(e01*e01 + e01);
            float a10 = q0*k1.x*INVS*(e10*e10 + e10);
            float a11 = q1*k1.y*INVS*(e11*e11 + e11);
            *(uint32_t*)(sm + ATT + nc*9216 + r0*144 + c_loc*2)     = hpk(a00, a01);
            *(uint32_t*)(sm + ATT + nc*9216 + (r0+8)*144 + c_loc*2) = hpk(a10, a11);
        }
    }

    // ================= softmax partials (overlaps Woe(0) load) =================
    __syncthreads();                          // all attn chunks visible
    float s = 0.f, ag = 0.f;
    {
        int c = tid;
        int ch = c >> 6, off = c & 63;
        const __half* vbase = g_v16 + (size_t)(b*Ndim + jrow0)*Cdim + c;
        #pragma unroll 4
        for (int j = 0; j < 64; j++) {
            float a = __half2float(*(const __half*)(sm + ATT + ch*9216 + j*144 + off*2));
            float p = __expf(a);
            s += p;
            ag += p * __half2float(vbase[(size_t)j*Cdim]);
        }
        g_ps [(size_t)jh*BN*Cdim + (size_t)bi*Cdim + c] = s;
        g_pag[(size_t)jh*BN*Cdim + (size_t)bi*Cdim + c] = ag;
    }

    // ================= Phase 2: GEMM2 n-chunks, write edge_out =================
    CP_WAIT0; __syncthreads();                // Woe(0) ready
    for (int mc = 0; mc < 4; mc++) {
        float acc2[4][4];
        #pragma unroll
        for (int i = 0; i < 4; i++)
            #pragma unroll
            for (int r = 0; r < 4; r++) acc2[i][r] = 0.f;

        gpass<true>(sb, aoff, atoff, boff, acc2);
        __syncthreads();                      // all done reading WB
        if (mc < 3) { loadW(sb, g_Woe_h + (size_t)(mc+1)*64*Cdim, tid); CP_COMMIT; }

        // write edge_out slice (overlaps next Woe load)
        float* out0 = edge_out + ((size_t)bi*Ndim + jrow0 + r0)*Cdim + mc*64;
        float* out1 = out0 + 8*Cdim;
        #pragma unroll
        for (int nt = 0; nt < 4; nt++) {
            int n = wn*32 + nt*8 + ((lane & 3) << 1);
            int nglob = mc*64 + n;
            float2 o0, o1;
            o0.x = acc2[nt][0] + sBoe[nglob];   o0.y = acc2[nt][1] + sBoe[nglob+1];
            o1.x = acc2[nt][2] + sBoe[nglob];   o1.y = acc2[nt][3] + sBoe[nglob+1];
            *(float2*)(out0 + n) = o0;
            *(float2*)(out1 + n) = o1;
        }
        if (mc < 3) { CP_WAIT0; __syncthreads(); }
    }

    // ---- second-arriving CTA per bi combines partials + node matvec ----
    __threadfence();
    __syncthreads();
    if (tid == 0) {
        int old = atomicAdd(&g_cnt[bi], 1);
        sWin = (old == 1);
        if (old == 1) g_cnt[bi] = 0;          // self-reset for next launch
    }
    __syncthreads();
    if (sWin) {
        __threadfence();                       // acquire other CTA's partials
        int c = tid;
        float so = g_ps [(size_t)(jh^1)*BN*Cdim + (size_t)bi*Cdim + c];
        float ao = g_pag[(size_t)(jh^1)*BN*Cdim + (size_t)bi*Cdim + c];
        sAgg[c] = (ag + ao) / (s + so);
        __syncthreads();
        float acc = bon[c];
        #pragma unroll 8
        for (int k = 0; k < Cdim; k++)
            acc = fmaf(sAgg[k], g_WonT[(size_t)k*Cdim + c], acc);
        node_out[(size_t)bi*Cdim + c] = acc;
    }
}

// ---------------- launch ----------------
extern "C" void kernel_launch(void* const* d_in, const int* in_sizes, int n_in,
                              void* d_out, int out_size)
{
    const float* node = (const float*)d_in[0];
    const float* edge = (const float*)d_in[1];
    const float* Wq  = (const float*)d_in[2];  const float* bq  = (const float*)d_in[3];
    const float* Wk  = (const float*)d_in[4];  const float* bk  = (const float*)d_in[5];
    const float* Wv  = (const float*)d_in[6];  const float* bv  = (const float*)d_in[7];
    const float* We  = (const float*)d_in[8];  const float* be  = (const float*)d_in[9];
    const float* Woe = (const float*)d_in[10]; const float* boe = (const float*)d_in[11];
    const float* Won = (const float*)d_in[12]; const float* bon = (const float*)d_in[13];

    float* out = (float*)d_out;
    float* node_out = out;                       // [B,N,C]
    float* edge_out = out + (size_t)BN*Cdim;     // [B,N,N,C]

    cudaFuncSetAttribute(edge_fused, cudaFuncAttributeMaxDynamicSharedMemorySize, ESMEM);

    prep_w<<<dim3(Cdim, 3), Cdim>>>(We, Woe, Won);
    proj_kernel<<<dim3(BN/64, 3), 256>>>(node, Wq, bq, Wk, bk, Wv, bv);
    edge_fused<<<2*BN, 256, ESMEM>>>(edge, be, boe, bon, edge_out, node_out);
}

// round 9
// speedup vs baseline: 1.0363x; 1.0363x over previous
#include <cuda_runtime.h>
#include <cuda_fp16.h>
#include <math.h>
#include <stdint.h>

#define Bdim 16
#define Ndim 128
#define Cdim 256
#define BN   2048
#define INVS 0.1767766952966369f

// ---------------- device globals ----------------
__device__ float g_q[BN*Cdim];
__device__ float g_k[BN*Cdim];
__device__ __align__(16) __half g_v16[BN*Cdim];
__device__ float g_WonT[Cdim*Cdim];
__device__ __align__(16) __half g_We_h[Cdim*Cdim];
__device__ __align__(16) __half g_Woe_h[Cdim*Cdim];
__device__ float g_ps [2*BN*Cdim];
__device__ float g_pag[2*BN*Cdim];
__device__ int   g_cnt[BN];          // zero-init; self-resetting per launch

// ---------------- smem layout (bytes) ----------------
#define EDG   0        // edge fp16 [64][264h] stride 528        = 33792
#define ATT   33792    // attn fp16 4 chunks x [64][72h] s144    = 36864
#define BS0   70656    // B slab buf0 [256 rows][48B]            = 12288
#define BS1   82944    // B slab buf1                            = 12288
#define SQ_   95232
#define SBE_  96256
#define SBOE_ 97280
#define SAGG_ 98304
#define ESMEM 99328

// ---------------- PTX helpers ----------------
__device__ __forceinline__ uint32_t smem_u32(const void* p) {
    uint32_t a;
    asm("{ .reg .u64 t; cvta.to.shared.u64 t, %1; cvt.u32.u64 %0, t; }" : "=r"(a) : "l"(p));
    return a;
}
__device__ __forceinline__ void ldm4(uint32_t addr, uint32_t r[4]) {
    asm volatile("ldmatrix.sync.aligned.m8n8.x4.shared.b16 {%0,%1,%2,%3}, [%4];"
                 : "=r"(r[0]), "=r"(r[1]), "=r"(r[2]), "=r"(r[3]) : "r"(addr));
}
__device__ __forceinline__ void mma_f16(float d[4], const uint32_t a[4],
                                        uint32_t b0, uint32_t b1) {
    asm volatile("mma.sync.aligned.m16n8k16.row.col.f32.f16.f16.f32 "
                 "{%0,%1,%2,%3}, {%4,%5,%6,%7}, {%8,%9}, {%0,%1,%2,%3};"
                 : "+f"(d[0]), "+f"(d[1]), "+f"(d[2]), "+f"(d[3])
                 : "r"(a[0]), "r"(a[1]), "r"(a[2]), "r"(a[3]), "r"(b0), "r"(b1));
}
__device__ __forceinline__ uint32_t hpk(float a, float b) {
    __half2 t = __floats2half2_rn(a, b);
    return *reinterpret_cast<uint32_t*>(&t);
}
__device__ __forceinline__ void cp16(uint32_t d, const void* s) {
    asm volatile("cp.async.cg.shared.global [%0], [%1], 16;" :: "r"(d), "l"(s));
}
#define CP_COMMIT asm volatile("cp.async.commit_group;" ::: "memory")
#define CP_WAIT0  asm volatile("cp.async.wait_group 0;" ::: "memory")
#define CP_WAIT1  asm volatile("cp.async.wait_group 1;" ::: "memory")

// ---------------- merged setup kernel: weight prep + qkv projection ----------------
#define SASTR 36
#define SBSTR 260

__global__ __launch_bounds__(256) void setup_kernel(
    const float* __restrict__ X,
    const float* __restrict__ W0, const float* __restrict__ b0,
    const float* __restrict__ W1, const float* __restrict__ b1,
    const float* __restrict__ W2, const float* __restrict__ b2,
    const float* __restrict__ We, const float* __restrict__ Woe,
    const float* __restrict__ Won)
{
    __shared__ float sA[64*SASTR];
    __shared__ float sB[32*SBSTR];
    int blk = blockIdx.x;
    int tid = threadIdx.x;

    if (blk < 768) {
        // ---- weight prep ----
        int n = blk & 255, w = blk >> 8, k = tid;
        if (w == 2) { g_WonT[k*Cdim + n] = Won[n*Cdim + k]; return; }
        const float* W = w ? Woe : We;
        __half hi = __float2half(W[n*Cdim + k]);
        if (w) g_Woe_h[n*Cdim+k] = hi;
        else   g_We_h [n*Cdim+k] = hi;
        return;
    }

    // ---- qkv projection ----
    int idx = blk - 768;                 // 0..95
    int which = idx >> 5;                // 0,1,2
    int row0 = (idx & 31) * 64;
    const float* W    = (which==0) ? W0 : (which==1 ? W1 : W2);
    const float* bias = (which==0) ? b0 : (which==1 ? b1 : b2);
    int tx = tid & 31, ty = tid >> 5;

    float acc[8][8];
    #pragma unroll
    for (int m = 0; m < 8; m++)
        #pragma unroll
        for (int n = 0; n < 8; n++) acc[m][n] = 0.f;

    for (int kc = 0; kc < 8; kc++) {
        __syncthreads();
        // load A tile
        #pragma unroll
        for (int it = 0; it < 2; it++) {
            int i2 = tid + it*256;
            int r = i2 >> 3, k4 = i2 & 7;
            float4 t = *(const float4*)(X + (size_t)(row0 + r)*Cdim + kc*32 + k4*4);
            *(float4*)(sA + r*SASTR + k4*4) = t;
        }
        // load B tile (transposed)
        #pragma unroll
        for (int it = 0; it < 8; it++) {
            int i2 = tid + it*256;
            int c = i2 >> 3, k4 = i2 & 7;
            float4 t = *(const float4*)(W + c*Cdim + kc*32 + k4*4);
            sB[(k4*4+0)*SBSTR + c] = t.x;
            sB[(k4*4+1)*SBSTR + c] = t.y;
            sB[(k4*4+2)*SBSTR + c] = t.z;
            sB[(k4*4+3)*SBSTR + c] = t.w;
        }
        __syncthreads();
        #pragma unroll
        for (int k = 0; k < 32; k++) {
            float a[8];
            #pragma unroll
            for (int mm = 0; mm < 4; mm++) {
                a[mm]   = sA[(ty*4+mm)*SASTR + k];
                a[4+mm] = sA[(32+ty*4+mm)*SASTR + k];
            }
            float4 p0 = *(const float4*)(sB + k*SBSTR + tx*4);
            float4 p1 = *(const float4*)(sB + k*SBSTR + 128 + tx*4);
            float bb[8] = {p0.x,p0.y,p0.z,p0.w,p1.x,p1.y,p1.z,p1.w};
            #pragma unroll
            for (int m = 0; m < 8; m++)
                #pragma unroll
                for (int n = 0; n < 8; n++)
                    acc[m][n] = fmaf(a[m], bb[n], acc[m][n]);
        }
    }
    #pragma unroll
    for (int mh = 0; mh < 2; mh++)
    #pragma unroll
    for (int mm = 0; mm < 4; mm++) {
        int m = mh*4 + mm;
        int rloc = mh*32 + ty*4 + mm;
        size_t grow = (size_t)(row0 + rloc) * Cdim;
        #pragma unroll
        for (int nh = 0; nh < 2; nh++) {
            int col0 = nh*128 + tx*4;
            float4 o;
            o.x = acc[m][nh*4+0] + bias[col0+0];
            o.y = acc[m][nh*4+1] + bias[col0+1];
            o.z = acc[m][nh*4+2] + bias[col0+2];
            o.w = acc[m][nh*4+3] + bias[col0+3];
            if (which == 0)      *(float4*)(g_q + grow + col0) = o;
            else if (which == 1) *(float4*)(g_k + grow + col0) = o;
            else {
                __half2 h0 = __floats2half2_rn(o.x, o.y);
                __half2 h1 = __floats2half2_rn(o.z, o.w);
                uint2 u;
                u.x = *reinterpret_cast<uint32_t*>(&h0);
                u.y = *reinterpret_cast<uint32_t*>(&h1);
                *(uint2*)(g_v16 + grow + col0) = u;
            }
        }
    }
}

// ---------------- B k-slab loader: W[n 0..255][k ks*16..+16] -> [256 rows][48B] ----------------
__device__ __forceinline__ void loadSlab(uint32_t sbuf, const __half* W, int ks, int tid) {
    #pragma unroll
    for (int it = 0; it < 2; it++) {
        int idx = tid + it*256;              // 0..511
        int row = idx >> 1, half = idx & 1;
        cp16(sbuf + row*48 + half*16, W + row*Cdim + ks*16 + half*8);
    }
}

// ---------------- one k16 slab of the 64x256 warp-tiled GEMM (m32 x n64 per warp) ----------------
template<bool FROM_ATT>
__device__ __forceinline__ void gslab(uint32_t aBase, uint32_t bBase, int ks,
                                      float acc[2][8][4]) {
    uint32_t a[2][4];
    #pragma unroll
    for (int mt = 0; mt < 2; mt++) {
        uint32_t aaddr;
        if (FROM_ATT) aaddr = aBase + (ks>>2)*9216 + (ks&3)*32 + mt*(16*144);
        else          aaddr = aBase + ks*32 + mt*(16*528);
        ldm4(aaddr, a[mt]);
    }
    #pragma unroll
    for (int t = 0; t < 4; t++) {
        uint32_t bf[4];
        ldm4(bBase + t*768, bf);
        #pragma unroll
        for (int mt = 0; mt < 2; mt++) {
            mma_f16(acc[mt][t*2+0], a[mt], bf[0], bf[1]);
            mma_f16(acc[mt][t*2+1], a[mt], bf[2], bf[3]);
        }
    }
}

// ---------------- fused edge mega-kernel: one CTA per (b,i,j-half) ----------------
__global__ __launch_bounds__(256, 2) void edge_fused(
    const float* __restrict__ edge,
    const float* __restrict__ be, const float* __restrict__ boe,
    const float* __restrict__ bon,
    float* __restrict__ edge_out, float* __restrict__ node_out)
{
    extern __shared__ char sm[];
    __shared__ int sWin;
    uint32_t sb = smem_u32(sm);
    const int tid  = threadIdx.x;
    const int lane = tid & 31, wid = tid >> 5;
    const int bi   = blockIdx.x >> 1;
    const int jh   = blockIdx.x & 1;
    const int b    = bi >> 7;
    const int jrow0 = jh * 64;

    // prologue: first two We slabs
    loadSlab(sb + BS0, g_We_h, 0, tid); CP_COMMIT;
    loadSlab(sb + BS1, g_We_h, 1, tid); CP_COMMIT;

    float* sQ   = (float*)(sm + SQ_);
    float* sBe  = (float*)(sm + SBE_);
    float* sBoe = (float*)(sm + SBOE_);
    float* sAgg = (float*)(sm + SAGG_);
    sQ[tid]   = g_q[(size_t)bi*Cdim + tid];
    sBe[tid]  = be[tid];
    sBoe[tid] = boe[tid];

    // edge half-tile -> fp16 in smem (64 rows x 256 cols)
    const float4* erow = (const float4*)(edge + ((size_t)bi*Ndim + jrow0)*Cdim);
    #pragma unroll
    for (int it = 0; it < 16; it++) {
        int idx = tid + it*256;
        float4 v = erow[idx];
        int j = idx >> 6, c4 = idx & 63;
        __half2 h0 = __floats2half2_rn(v.x, v.y);
        __half2 h1 = __floats2half2_rn(v.z, v.w);
        uint2 u;
        u.x = *reinterpret_cast<uint32_t*>(&h0);
        u.y = *reinterpret_cast<uint32_t*>(&h1);
        *(uint2*)(sm + EDG + j*528 + c4*8) = u;
    }

    // warp grid: 2 m-groups x 4 n-groups; warp tile m32 x n64
    const int wm = wid & 1, wn = wid >> 1;
    const uint32_t aoffE = sb + EDG + (uint32_t)((wm*32 + (lane & 15))*528 + ((lane >> 4) << 4));
    const uint32_t aoffT = sb + ATT + (uint32_t)((wm*32 + (lane & 15))*144 + ((lane >> 4) << 4));
    const uint32_t boff  = (uint32_t)((wn*64 + (lane & 7) + ((lane & 16) ? 8 : 0))*48 + ((lane & 8) << 1));

    float acc[2][8][4];
    #pragma unroll
    for (int mt = 0; mt < 2; mt++)
        #pragma unroll
        for (int g = 0; g < 8; g++)
            #pragma unroll
            for (int r = 0; r < 4; r++) acc[mt][g][r] = 0.f;

    // ================= GEMM1: e = edge @ We^T (streamed k16 slabs) =================
    for (int ks = 0; ks < 16; ks++) {
        if (ks < 15) { CP_WAIT1; } else { CP_WAIT0; }
        __syncthreads();                                   // slab ks visible (ks=0: +EDG/sQ)
        gslab<false>(aoffE, sb + ((ks & 1) ? BS1 : BS0) + boff, ks, acc);
        __syncthreads();                                   // all warps done with buffer
        if (ks < 14) { loadSlab(sb + ((ks & 1) ? BS1 : BS0), g_We_h, ks + 2, tid); CP_COMMIT; }
    }

    // prefetch first two Woe slabs (overlap gating epilogue)
    loadSlab(sb + BS0, g_Woe_h, 0, tid); CP_COMMIT;
    loadSlab(sb + BS1, g_Woe_h, 1, tid); CP_COMMIT;

    // ================= gating epilogue -> ATT; reset acc for GEMM2 =================
    #pragma unroll
    for (int mt = 0; mt < 2; mt++) {
        int rbase = wm*32 + mt*16 + (lane >> 2);
        const float* k0p = g_k + (size_t)(b*Ndim + jrow0 + rbase)*Cdim;
        const float* k1p = k0p + 8*Cdim;
        #pragma unroll
        for (int t = 0; t < 8; t++) {
            int c_loc = t*8 + ((lane & 3) << 1);
            int c = wn*64 + c_loc;
            float2 kk0 = *(const float2*)(k0p + c);
            float2 kk1 = *(const float2*)(k1p + c);
            float q0 = sQ[c], q1 = sQ[c+1];
            float be0 = sBe[c], be1 = sBe[c+1];
            float e00 = acc[mt][t][0] + be0, e01 = acc[mt][t][1] + be1;
            float e10 = acc[mt][t][2] + be0, e11 = acc[mt][t][3] + be1;
            float a00 = q0*kk0.x*INVS*(e00*e00 + e00);
            float a01 = q1*kk0.y*INVS*(e01*e01 + e01);
            float a10 = q0*kk1.x*INVS*(e10*e10 + e10);
            float a11 = q1*kk1.y*INVS*(e11*e11 + e11);
            *(uint32_t*)(sm + ATT + wn*9216 + rbase*144 + c_loc*2)     = hpk(a00, a01);
            *(uint32_t*)(sm + ATT + wn*9216 + (rbase+8)*144 + c_loc*2) = hpk(a10, a11);
            acc[mt][t][0] = 0.f; acc[mt][t][1] = 0.f;
            acc[mt][t][2] = 0.f; acc[mt][t][3] = 0.f;
        }
    }

    // ================= GEMM2: edge_out = attn @ Woe^T (streamed k16 slabs) =================
    for (int ks = 0; ks < 16; ks++) {
        if (ks < 15) { CP_WAIT1; } else { CP_WAIT0; }
        __syncthreads();                                   // slab ks + (ks=0: ATT) visible
        gslab<true>(aoffT, sb + ((ks & 1) ? BS1 : BS0) + boff, ks, acc);
        __syncthreads();
        if (ks < 14) { loadSlab(sb + ((ks & 1) ? BS1 : BS0), g_Woe_h, ks + 2, tid); CP_COMMIT; }
    }

    // ---- edge_out epilogue ----
    #pragma unroll
    for (int mt = 0; mt < 2; mt++) {
        int rbase = wm*32 + mt*16 + (lane >> 2);
        float* out0 = edge_out + ((size_t)bi*Ndim + jrow0 + rbase)*Cdim;
        float* out1 = out0 + 8*Cdim;
        #pragma unroll
        for (int t = 0; t < 8; t++) {
            int n = wn*64 + t*8 + ((lane & 3) << 1);
            float2 o0, o1;
            o0.x = acc[mt][t][0] + sBoe[n];   o0.y = acc[mt][t][1] + sBoe[n+1];
            o1.x = acc[mt][t][2] + sBoe[n];   o1.y = acc[mt][t][3] + sBoe[n+1];
            *(float2*)(out0 + n) = o0;
            *(float2*)(out1 + n) = o1;
        }
    }

    // ---- local softmax partials over 64 j ----
    float s = 0.f, ag = 0.f;
    {
        int c = tid;
        int ch = c >> 6, off = c & 63;
        const __half* vbase = g_v16 + (size_t)(b*Ndim + jrow0)*Cdim + c;
        #pragma unroll 4
        for (int j = 0; j < 64; j++) {
            float a = __half2float(*(const __half*)(sm + ATT + ch*9216 + j*144 + off*2));
            float p = __expf(a);
            s += p;
            ag += p * __half2float(vbase[(size_t)j*Cdim]);
        }
        g_ps [(size_t)jh*BN*Cdim + (size_t)bi*Cdim + c] = s;
        g_pag[(size_t)jh*BN*Cdim + (size_t)bi*Cdim + c] = ag;
    }

    // ---- second-arriving CTA per bi combines partials + node matvec ----
    __threadfence();
    __syncthreads();
    if (tid == 0) {
        int old = atomicAdd(&g_cnt[bi], 1);
        sWin = (old == 1);
        if (old == 1) g_cnt[bi] = 0;
    }
    __syncthreads();
    if (sWin) {
        __threadfence();
        int c = tid;
        float so = g_ps [(size_t)(jh^1)*BN*Cdim + (size_t)bi*Cdim + c];
        float ao = g_pag[(size_t)(jh^1)*BN*Cdim + (size_t)bi*Cdim + c];
        sAgg[c] = (ag + ao) / (s + so);
        __syncthreads();
        float accn = bon[c];
        #pragma unroll 8
        for (int k = 0; k < Cdim; k++)
            accn = fmaf(sAgg[k], g_WonT[(size_t)k*Cdim + c], accn);
        node_out[(size_t)bi*Cdim + c] = accn;
    }
}

// ---------------- launch ----------------
extern "C" void kernel_launch(void* const* d_in, const int* in_sizes, int n_in,
                              void* d_out, int out_size)
{
    const float* node = (const float*)d_in[0];
    const float* edge = (const float*)d_in[1];
    const float* Wq  = (const float*)d_in[2];  const float* bq  = (const float*)d_in[3];
    const float* Wk  = (const float*)d_in[4];  const float* bk  = (const float*)d_in[5];
    const float* Wv  = (const float*)d_in[6];  const float* bv  = (const float*)d_in[7];
    const float* We  = (const float*)d_in[8];  const float* be  = (const float*)d_in[9];
    const float* Woe = (const float*)d_in[10]; const float* boe = (const float*)d_in[11];
    const float* Won = (const float*)d_in[12]; const float* bon = (const float*)d_in[13];

    float* out = (float*)d_out;
    float* node_out = out;                       // [B,N,C]
    float* edge_out = out + (size_t)BN*Cdim;     // [B,N,N,C]

    cudaFuncSetAttribute(edge_fused, cudaFuncAttributeMaxDynamicSharedMemorySize, ESMEM);

    setup_kernel<<<768 + 96, 256>>>(node, Wq, bq, Wk, bk, Wv, bv, We, Woe, Won);
    edge_fused<<<2*BN, 256, ESMEM>>>(edge, be, boe, bon, edge_out, node_out);
}